// round 15
// baseline (speedup 1.0000x reference)
#include <cuda_runtime.h>
#include <cuda_bf16.h>
#include <cstdint>
#include <math.h>

// ---------------- problem constants ----------------
#define TOK   131072          // B*N*NH tokens
#define MDIM  512
#define FFD   2048
#define MCNT  4096
#define NH    32
#define HEADS 8
#define HD    64

// ---------------- helpers ----------------
__device__ __forceinline__ uint32_t smem_to_u32(const void* p){
    uint32_t a;
    asm("{ .reg .u64 t; cvta.to.shared.u64 t, %1; cvt.u32.u64 %0, t; }" : "=r"(a) : "l"(p));
    return a;
}
__device__ __forceinline__ void cp_async16(uint32_t saddr, const void* gaddr){
    asm volatile("cp.async.cg.shared.global [%0], [%1], 16;" :: "r"(saddr), "l"(gaddr));
}
__device__ __forceinline__ void cp_commit(){ asm volatile("cp.async.commit_group;"); }
template<int N>
__device__ __forceinline__ void cp_wait(){ asm volatile("cp.async.wait_group %0;" :: "n"(N)); }

__device__ __forceinline__ void ldm_x4(uint32_t addr, uint32_t& r0, uint32_t& r1,
                                       uint32_t& r2, uint32_t& r3){
    asm volatile("ldmatrix.sync.aligned.m8n8.x4.shared.b16 {%0,%1,%2,%3}, [%4];"
        : "=r"(r0), "=r"(r1), "=r"(r2), "=r"(r3) : "r"(addr));
}
__device__ __forceinline__ void mma_bf16(float& c0, float& c1, float& c2, float& c3,
                                         uint32_t a0, uint32_t a1, uint32_t a2, uint32_t a3,
                                         uint32_t b0, uint32_t b1){
    asm volatile("mma.sync.aligned.m16n8k16.row.col.f32.bf16.bf16.f32 "
        "{%0,%1,%2,%3}, {%4,%5,%6,%7}, {%8,%9}, {%0,%1,%2,%3};"
        : "+f"(c0), "+f"(c1), "+f"(c2), "+f"(c3)
        : "r"(a0), "r"(a1), "r"(a2), "r"(a3), "r"(b0), "r"(b1));
}
__device__ __forceinline__ void split2(float f, __nv_bfloat16& h, __nv_bfloat16& l){
    h = __float2bfloat16(f);
    l = __float2bfloat16(f - __bfloat162float(h));
}

// ---------------- scratch (~2.3 GB) ----------------
__device__ __align__(256) float g_f0 [TOK*MDIM];          // h (residual)
__device__ __align__(256) float g_qkv[(size_t)TOK*1536];  // qkv / att_out / h1 / ff2
__device__ __align__(256) __nv_bfloat16 g_a1[(size_t)TOK*1024];  // split 512-wide acts
__device__ __align__(256) __nv_bfloat16 g_a2[(size_t)TOK*4096];  // split ff / x acts
__device__ __align__(256) __nv_bfloat16 g_win2 [512*256];
__device__ __align__(256) __nv_bfloat16 g_wqkv2[(size_t)1536*1024];
__device__ __align__(256) __nv_bfloat16 g_wo2  [512*1024];
__device__ __align__(256) __nv_bfloat16 g_wf12 [(size_t)2048*1024];
__device__ __align__(256) __nv_bfloat16 g_wf22 [(size_t)512*4096];
__device__ __align__(256) __nv_bfloat16 g_wout2[128*1024];

// ---------------- fused weight conversion (ONE launch for all 8) ----------
struct WtDesc { const float* W; __nv_bfloat16* Y; int K; int N; };
struct WtTable { WtDesc d[8]; };

__global__ void __launch_bounds__(256)
split_wt_all(WtTable tab)
{
    const WtDesc& e = tab.d[blockIdx.y];
    size_t total = (size_t)e.N * 2 * e.K;
    size_t id = (size_t)blockIdx.x * 256 + threadIdx.x;
    if (id >= total) return;
    int K2 = 2 * e.K;
    size_t n = id / K2;
    int c = (int)(id % K2);
    int reg = c >= e.K, cs = c - (reg ? e.K : 0);
    float x = e.W[(size_t)cs * e.N + n];
    __nv_bfloat16 h, l;
    split2(x, h, l);
    e.Y[id] = reg ? l : h;
}

// ---------------- split conversion: activations (x only) ----------------
__global__ void __launch_bounds__(256)
split_act(const float* __restrict__ X, __nv_bfloat16* __restrict__ Y,
          int K, size_t total /* R*K/4 */)
{
    size_t id = (size_t)blockIdx.x * 256 + threadIdx.x;
    if (id >= total) return;
    int kq = K >> 2;
    size_t r = id / kq;
    int c = (int)(id % kq) << 2;
    float4 x = *(const float4*)(X + r * K + c);
    __nv_bfloat16 h0,h1,h2,h3,l0,l1,l2,l3;
    split2(x.x,h0,l0); split2(x.y,h1,l1); split2(x.z,h2,l2); split2(x.w,h3,l3);
    __nv_bfloat162 hA = __halves2bfloat162(h0,h1), hB = __halves2bfloat162(h2,h3);
    __nv_bfloat162 lA = __halves2bfloat162(l0,l1), lB = __halves2bfloat162(l2,l3);
    size_t ob = r * (size_t)(2 * K);
    *(uint2*)(Y + ob + c)     = make_uint2(*(uint32_t*)&hA, *(uint32_t*)&hB);
    *(uint2*)(Y + ob + K + c) = make_uint2(*(uint32_t*)&lA, *(uint32_t*)&lB);
}

// ---------------- mma.sync bf16 GEMM, 5-tile split schedule ----------------
// A [M, 2K] = [hi|lo], Bt [Ntot, 2K] = [hi|lo] (K-major rows).
// Per 64-wide K-group g, three chunks reordered to reuse Ahi:
//   t%3==0: load Ahi(g)->A0, Bhi(g)->B[s]   compute Ahi*Bhi
//   t%3==1: load           Blo(g)->B[s']    compute Ahi*Blo  (A0 reused)
//   t%3==2: load Alo(g)->A1, Bhi(g)->B[s]   compute Alo*Bhi
// 5 tile loads per group instead of 6 (-17% global/STS traffic).
// CTA tile 128x128; 4 warps (2x2); warp tile 64x64; BK=64; 144-byte row
// stride (affine, conflict-free); A ring 2 slots + B ring 2 slots = 73.7KB;
// 128 threads -> 3 CTAs/SM. mode: 0=f32, 1=silu+split, 2=f32+split.
__global__ void __launch_bounds__(128, 3)
mma_gemm(const __nv_bfloat16* __restrict__ A, const __nv_bfloat16* __restrict__ Bt,
         float* __restrict__ Cf, __nv_bfloat16* __restrict__ Csp,
         int K, int Ntot, int mode)
{
    constexpr int THREADS = 128;
    constexpr int ROWB = 144;                 // bytes per smem row
    constexpr int A_BYTES = 128 * ROWB;       // 18432 (one tile)
    extern __shared__ __align__(16) char smem[];

    const int tid  = threadIdx.x;
    const int lane = tid & 31;
    const int wid  = tid >> 5;
    const int wm   = wid >> 1;        // 0..1
    const int wn   = wid & 1;         // 0..1
    const int m0   = blockIdx.y * 128;
    const int n0   = blockIdx.x * 128;

    const int lda = 2 * K;
    const __nv_bfloat16* Ab = A  + (size_t)m0 * lda;
    const __nv_bfloat16* Bb = Bt + (size_t)n0 * lda;
    const uint32_t sbase = smem_to_u32(smem);
    // slots: A0 @0, A1 @A_BYTES, B0 @2*A_BYTES, B1 @3*A_BYTES

    float c[4][8][4];
    #pragma unroll
    for (int i = 0; i < 4; i++)
        #pragma unroll
        for (int j = 0; j < 8; j++)
            #pragma unroll
            for (int q = 0; q < 4; q++) c[i][j][q] = 0.f;

    const int kch = K >> 6;       // 64-wide K groups
    const int nch = 3 * kch;

    auto load_chunk = [&](int tt){
        int g = tt / 3;
        int r = tt - g * 3;
        if (r != 1){
            int ac = ((r == 2) ? K : 0) + (g << 6);
            uint32_t sa = sbase + ((r == 2) ? A_BYTES : 0);
            #pragma unroll
            for (int it = 0; it < 8; it++){
                int idx = tid + it * THREADS;
                int rr = idx >> 3, ch = idx & 7;
                cp_async16(sa + rr * ROWB + ch * 16, Ab + (size_t)rr * lda + ac + ch * 8);
            }
        }
        int bc = ((r == 1) ? K : 0) + (g << 6);
        uint32_t sb = sbase + 2 * A_BYTES + (((g + r) & 1) ? A_BYTES : 0);
        #pragma unroll
        for (int it = 0; it < 8; it++){
            int idx = tid + it * THREADS;
            int rr = idx >> 3, ch = idx & 7;
            cp_async16(sb + rr * ROWB + ch * 16, Bb + (size_t)rr * lda + bc + ch * 8);
        }
    };

    load_chunk(0);
    cp_commit();

    for (int t = 0; t < nch; t++){
        cp_wait<0>();
        __syncthreads();
        if (t + 1 < nch){
            load_chunk(t + 1);
            cp_commit();
        }
        const int g = t / 3;
        const int r = t - g * 3;
        const uint32_t sa = sbase + ((r == 2) ? A_BYTES : 0);
        const uint32_t sb = sbase + 2 * A_BYTES + (((g + r) & 1) ? A_BYTES : 0);
        #pragma unroll
        for (int ks = 0; ks < 4; ks++){
            uint32_t a[4][4], b[8][2];
            #pragma unroll
            for (int mf = 0; mf < 4; mf++){
                int rr = wm * 64 + mf * 16 + (lane & 15);
                int ch = 2 * ks + (lane >> 4);
                ldm_x4(sa + rr * ROWB + ch * 16,
                       a[mf][0], a[mf][1], a[mf][2], a[mf][3]);
            }
            #pragma unroll
            for (int gg = 0; gg < 4; gg++){
                int rr = wn * 64 + gg * 16 + ((lane >> 4) << 3) + (lane & 7);
                int ch = 2 * ks + ((lane >> 3) & 1);
                ldm_x4(sb + rr * ROWB + ch * 16,
                       b[2*gg][0], b[2*gg][1], b[2*gg+1][0], b[2*gg+1][1]);
            }
            #pragma unroll
            for (int mf = 0; mf < 4; mf++)
                #pragma unroll
                for (int nf = 0; nf < 8; nf++)
                    mma_bf16(c[mf][nf][0], c[mf][nf][1], c[mf][nf][2], c[mf][nf][3],
                             a[mf][0], a[mf][1], a[mf][2], a[mf][3],
                             b[nf][0], b[nf][1]);
        }
    }

    // epilogue
    #pragma unroll
    for (int mf = 0; mf < 4; mf++){
        #pragma unroll
        for (int half = 0; half < 2; half++){
            const int row = m0 + wm * 64 + mf * 16 + (lane >> 2) + half * 8;
            #pragma unroll
            for (int nf = 0; nf < 8; nf++){
                const int col = n0 + wn * 64 + nf * 8 + (lane & 3) * 2;
                float fx = c[mf][nf][half * 2 + 0];
                float fy = c[mf][nf][half * 2 + 1];
                if (mode == 1){
                    fx = fx / (1.f + __expf(-fx));
                    fy = fy / (1.f + __expf(-fy));
                }
                if (mode != 1){
                    *(float2*)&Cf[(size_t)row * Ntot + col] = make_float2(fx, fy);
                }
                if (mode != 0){
                    __nv_bfloat16 hx, hy, lx, ly;
                    split2(fx, hx, lx);
                    split2(fy, hy, ly);
                    __nv_bfloat162 hp = __halves2bfloat162(hx, hy);
                    __nv_bfloat162 lp = __halves2bfloat162(lx, ly);
                    size_t rb = (size_t)row * (2 * Ntot);
                    *(__nv_bfloat162*)&Csp[rb + col]        = hp;
                    *(__nv_bfloat162*)&Csp[rb + Ntot + col] = lp;
                }
            }
        }
    }
}

// ---------------- fused attention: one block per m, all 8 heads ------------
__global__ void __launch_bounds__(256)
attn_kernel(const float* __restrict__ qkv,
            const int*   __restrict__ dist, const int* __restrict__ phi,
            const float* __restrict__ dtab, const float* __restrict__ ptab,
            const float* __restrict__ Wb,   __nv_bfloat16* __restrict__ osp)
{
    extern __shared__ float sm[];
    float* bias8 = sm;              // [h*1056 + i*33 + j]  (8448)
    float* qs    = sm + 8448;       // [i*68 + d]           (2176)
    float* ks    = sm + 10624;      // (2176)
    float* vs    = sm + 12800;      // (2176)
    float* sc    = sm + 14976;      // [i*33 + j]           (1056)
    float* wb8   = sm + 16032;      // [p*8 + h]            (256)

    const int m = blockIdx.x;
    const int t = threadIdx.x;

    wb8[t] = Wb[t];                 // 256 = PED*HEADS
    __syncthreads();

    // ---- bias for all heads: 4 pairs per thread ----
    const int base_mm = m * (NH * NH);
    #pragma unroll
    for (int q4 = 0; q4 < 4; q4++){
        int pair = t * 4 + q4;              // 0..1023
        int i = pair >> 5, j = pair & 31;
        int id = dist[base_mm + pair];
        int ip = phi [base_mm + pair];
        const float4* dp = (const float4*)(dtab + (size_t)id * 32);
        const float4* fp = (const float4*)(ptab + (size_t)ip * 32);
        float acc[8];
        #pragma unroll
        for (int h = 0; h < 8; h++) acc[h] = 0.f;
        #pragma unroll
        for (int v4 = 0; v4 < 8; v4++){
            float4 d4 = dp[v4];
            float4 f4 = fp[v4];
            float pr[4] = { d4.x*f4.x, d4.y*f4.y, d4.z*f4.z, d4.w*f4.w };
            #pragma unroll
            for (int pp = 0; pp < 4; pp++){
                int p = v4 * 4 + pp;
                #pragma unroll
                for (int h = 0; h < 8; h++)
                    acc[h] += pr[pp] * wb8[p * 8 + h];
            }
        }
        #pragma unroll
        for (int h = 0; h < 8; h++) bias8[h * 1056 + i * 33 + j] = acc[h];
    }

    const int i = t >> 3;          // row 0..31
    const int g = t & 7;           // group 0..7

    for (int h = 0; h < 8; h++){
        __syncthreads();   // bias ready (h=0) / prior head done (h>0)
        // load q,k,v head slices (32 rows x 16 float4 each), vectorized
        #pragma unroll
        for (int it = 0; it < 2; it++){
            int idx = t + it * 256;        // 0..511
            int r  = idx >> 4;             // row 0..31
            int c4 = idx & 15;             // float4 within row 0..15
            size_t gb = (size_t)(m * NH + r) * 1536 + h * 64 + c4 * 4;
            *(float4*)(qs + r * 68 + c4 * 4) = *(const float4*)(qkv + gb);
            *(float4*)(ks + r * 68 + c4 * 4) = *(const float4*)(qkv + gb + 512);
            *(float4*)(vs + r * 68 + c4 * 4) = *(const float4*)(qkv + gb + 1024);
        }
        __syncthreads();

        // scores: 4 j's per thread; q row loaded once per d4 (outer d loop)
        float sv[4] = {0.f, 0.f, 0.f, 0.f};
        #pragma unroll
        for (int d4 = 0; d4 < 16; d4++){
            float4 qa = *(float4*)(qs + i * 68 + d4 * 4);
            #pragma unroll
            for (int jj = 0; jj < 4; jj++){
                float4 ka = *(float4*)(ks + (g * 4 + jj) * 68 + d4 * 4);
                sv[jj] += qa.x*ka.x + qa.y*ka.y + qa.z*ka.z + qa.w*ka.w;
            }
        }
        #pragma unroll
        for (int jj = 0; jj < 4; jj++)
            sv[jj] = sv[jj] * 0.125f + bias8[h * 1056 + i * 33 + g * 4 + jj];

        // softmax across the 8 threads of row i
        float mx = fmaxf(fmaxf(sv[0], sv[1]), fmaxf(sv[2], sv[3]));
        mx = fmaxf(mx, __shfl_xor_sync(0xffffffffu, mx, 1));
        mx = fmaxf(mx, __shfl_xor_sync(0xffffffffu, mx, 2));
        mx = fmaxf(mx, __shfl_xor_sync(0xffffffffu, mx, 4));
        float ev[4], sum = 0.f;
        #pragma unroll
        for (int jj = 0; jj < 4; jj++){ ev[jj] = __expf(sv[jj] - mx); sum += ev[jj]; }
        sum += __shfl_xor_sync(0xffffffffu, sum, 1);
        sum += __shfl_xor_sync(0xffffffffu, sum, 2);
        sum += __shfl_xor_sync(0xffffffffu, sum, 4);
        const float inv = 1.f / sum;
        #pragma unroll
        for (int jj = 0; jj < 4; jj++) sc[i * 33 + g * 4 + jj] = ev[jj] * inv;
        __syncwarp();

        // AV: thread owns d-segment g*8 .. g*8+7 of row i
        const int dseg = g * 8;
        float acc[8];
        #pragma unroll
        for (int dd = 0; dd < 8; dd++) acc[dd] = 0.f;
        for (int j = 0; j < NH; j++){
            float p = sc[i * 33 + j];
            float4 v0 = *(float4*)(vs + j * 68 + dseg);
            float4 v1 = *(float4*)(vs + j * 68 + dseg + 4);
            acc[0] += p * v0.x; acc[1] += p * v0.y;
            acc[2] += p * v0.z; acc[3] += p * v0.w;
            acc[4] += p * v1.x; acc[5] += p * v1.y;
            acc[6] += p * v1.z; acc[7] += p * v1.w;
        }
        // split-bf16 output, row stride 1024 = [hi(512) | lo(512)]
        size_t rb = ((size_t)(m * NH) + i) * 1024 + h * 64 + dseg;
        #pragma unroll
        for (int dd = 0; dd < 8; dd += 2){
            __nv_bfloat16 hx, hy, lx, ly;
            split2(acc[dd],   hx, lx);
            split2(acc[dd+1], hy, ly);
            *(__nv_bfloat162*)&osp[rb + dd]       = __halves2bfloat162(hx, hy);
            *(__nv_bfloat162*)&osp[rb + 512 + dd] = __halves2bfloat162(lx, ly);
        }
    }
}

// ---------------- fused residual add + LayerNorm (+optional split out) ----
__global__ void __launch_bounds__(128)
add_ln_kernel2(const float* __restrict__ a, const float* __restrict__ b,
               const float* __restrict__ g, const float* __restrict__ be,
               float* __restrict__ outf, __nv_bfloat16* __restrict__ outsp)
{
    const int row = blockIdx.x;
    const int t   = threadIdx.x;
    const size_t off = (size_t)row * MDIM + t * 4;

    float4 va = *(const float4*)(a + off);
    float4 vb = *(const float4*)(b + off);
    float4 vv = make_float4(va.x + vb.x, va.y + vb.y, va.z + vb.z, va.w + vb.w);

    float s  = vv.x + vv.y + vv.z + vv.w;
    float ss = vv.x*vv.x + vv.y*vv.y + vv.z*vv.z + vv.w*vv.w;
    #pragma unroll
    for (int o2 = 16; o2; o2 >>= 1){
        s  += __shfl_xor_sync(0xffffffffu, s,  o2);
        ss += __shfl_xor_sync(0xffffffffu, ss, o2);
    }
    __shared__ float sh_s[4], sh_ss[4];
    const int w = t >> 5, l = t & 31;
    if (l == 0){ sh_s[w] = s; sh_ss[w] = ss; }
    __syncthreads();
    s  = sh_s[0]  + sh_s[1]  + sh_s[2]  + sh_s[3];
    ss = sh_ss[0] + sh_ss[1] + sh_ss[2] + sh_ss[3];

    const float mean = s * (1.f / 512.f);
    const float var  = ss * (1.f / 512.f) - mean * mean;
    const float rstd = rsqrtf(var + 1e-5f);

    float4 vg  = *(const float4*)(g  + t*4);
    float4 vbe = *(const float4*)(be + t*4);
    float4 r;
    r.x = (vv.x - mean) * rstd * vg.x + vbe.x;
    r.y = (vv.y - mean) * rstd * vg.y + vbe.y;
    r.z = (vv.z - mean) * rstd * vg.z + vbe.z;
    r.w = (vv.w - mean) * rstd * vg.w + vbe.w;
    if (outf) *(float4*)(outf + off) = r;
    if (outsp){
        __nv_bfloat16 h0,h1,h2,h3,l0,l1,l2,l3;
        split2(r.x,h0,l0); split2(r.y,h1,l1); split2(r.z,h2,l2); split2(r.w,h3,l3);
        __nv_bfloat162 hA = __halves2bfloat162(h0,h1), hB = __halves2bfloat162(h2,h3);
        __nv_bfloat162 lA = __halves2bfloat162(l0,l1), lB = __halves2bfloat162(l2,l3);
        size_t rb = (size_t)row * 1024 + t * 4;
        *(uint2*)(outsp + rb)       = make_uint2(*(uint32_t*)&hA, *(uint32_t*)&hB);
        *(uint2*)(outsp + rb + 512) = make_uint2(*(uint32_t*)&lA, *(uint32_t*)&lB);
    }
}

// ---------------- driver ----------------
extern "C" void kernel_launch(void* const* d_in, const int* in_sizes, int n_in,
                              void* d_out, int out_size)
{
    (void)in_sizes; (void)n_in; (void)out_size;

    const float* x    = (const float*)d_in[0];
    const int*   dist = (const int*)  d_in[1];
    const int*   phis = (const int*)  d_in[2];
    const float* W_in = (const float*)d_in[3];
    const float* dtab = (const float*)d_in[4];
    const float* ptab = (const float*)d_in[5];
    const float* Wb   = (const float*)d_in[6];
    const float* Wq   = (const float*)d_in[7];
    const float* Wk   = (const float*)d_in[8];
    const float* Wv   = (const float*)d_in[9];
    const float* Wo   = (const float*)d_in[10];
    const float* Wf1  = (const float*)d_in[11];
    const float* Wf2  = (const float*)d_in[12];
    const float* g1   = (const float*)d_in[13];
    const float* b1   = (const float*)d_in[14];
    const float* g2   = (const float*)d_in[15];
    const float* b2   = (const float*)d_in[16];
    const float* Wout = (const float*)d_in[17];
    float* out = (float*)d_out;

    float *pf0, *pqkv;
    __nv_bfloat16 *pa1, *pa2, *pwin, *pwqkv, *pwo, *pwf1, *pwf2, *pwout;
    cudaGetSymbolAddress((void**)&pf0,  g_f0);
    cudaGetSymbolAddress((void**)&pqkv, g_qkv);
    cudaGetSymbolAddress((void**)&pa1,  g_a1);
    cudaGetSymbolAddress((void**)&pa2,  g_a2);
    cudaGetSymbolAddress((void**)&pwin, g_win2);
    cudaGetSymbolAddress((void**)&pwqkv,g_wqkv2);
    cudaGetSymbolAddress((void**)&pwo,  g_wo2);
    cudaGetSymbolAddress((void**)&pwf1, g_wf12);
    cudaGetSymbolAddress((void**)&pwf2, g_wf22);
    cudaGetSymbolAddress((void**)&pwout,g_wout2);

    float* att_out = pqkv;                       // aliases (sequential deps)
    float* h1      = pqkv + (size_t)TOK * 512;
    float* ff2     = pqkv + (size_t)TOK * 1024;

    const int SMG = 4 * 128 * 144;          // 73728 per CTA (3 CTAs/SM)
    const int SMA = 16288 * 4;              // 65152 (attention)
    cudaFuncSetAttribute(mma_gemm, cudaFuncAttributeMaxDynamicSharedMemorySize, SMG);
    cudaFuncSetAttribute(attn_kernel, cudaFuncAttributeMaxDynamicSharedMemorySize, SMA);

    const unsigned MT = TOK / 128;   // 1024 m-tiles

    // 0) all weight conversions in one launch
    WtTable tab;
    tab.d[0] = { W_in, pwin,                      128,  512 };
    tab.d[1] = { Wq,   pwqkv,                     512,  512 };
    tab.d[2] = { Wk,   pwqkv + (size_t)512*1024,  512,  512 };
    tab.d[3] = { Wv,   pwqkv + (size_t)1024*1024, 512,  512 };
    tab.d[4] = { Wo,   pwo,                       512,  512 };
    tab.d[5] = { Wf1,  pwf1,                      512, 2048 };
    tab.d[6] = { Wf2,  pwf2,                     2048,  512 };
    tab.d[7] = { Wout, pwout,                     512,  128 };
    split_wt_all<<<dim3(8192, 8), 256>>>(tab);

    // 1) split x -> a2  [TOK, 256]
    {
        size_t total = (size_t)TOK * 128 / 4;
        split_act<<<(unsigned)((total + 255) / 256), 256>>>(x, pa2, 128, total);
    }
    // 2) h = x @ W_in -> f0 (fp32) + split -> a1
    mma_gemm<<<dim3(4, MT), 128, SMG>>>(pa2, pwin, pf0, pa1, 128, 512, 2);
    // 3) qkv = h @ Wqkv -> fp32 [TOK,1536]
    mma_gemm<<<dim3(12, MT), 128, SMG>>>(pa1, pwqkv, pqkv, nullptr, 512, 1536, 0);
    // 4) attention -> split o -> a1
    attn_kernel<<<MCNT, 256, SMA>>>(pqkv, dist, phis, dtab, ptab, Wb, pa1);
    // 5) att_out = o @ Wo -> fp32
    mma_gemm<<<dim3(4, MT), 128, SMG>>>(pa1, pwo, att_out, nullptr, 512, 512, 0);
    // 6) h1 = LN(h + att_out) -> fp32 h1 + split -> a1
    add_ln_kernel2<<<TOK, 128>>>(pf0, att_out, g1, b1, h1, pa1);
    // 7) ff = silu(h1 @ Wf1) -> split -> a2
    mma_gemm<<<dim3(16, MT), 128, SMG>>>(pa1, pwf1, nullptr, pa2, 512, 2048, 1);
    // 8) ff2 = ff @ Wf2 -> fp32
    mma_gemm<<<dim3(4, MT), 128, SMG>>>(pa2, pwf2, ff2, nullptr, 2048, 512, 0);
    // 9) h2 = LN(h1 + ff2) -> split only -> a1
    add_ln_kernel2<<<TOK, 128>>>(h1, ff2, g2, b2, nullptr, pa1);
    // 10) out = h2 @ W_out
    mma_gemm<<<dim3(1, MT), 128, SMG>>>(pa1, pwout, out, nullptr, 512, 128, 0);
}

// round 16
// speedup vs baseline: 1.0766x; 1.0766x over previous
#include <cuda_runtime.h>
#include <cuda_bf16.h>
#include <cstdint>
#include <math.h>

// ---------------- problem constants ----------------
#define TOK   131072          // B*N*NH tokens
#define MDIM  512
#define FFD   2048
#define MCNT  4096
#define NH    32
#define HEADS 8
#define HD    64

// ---------------- helpers ----------------
__device__ __forceinline__ uint32_t smem_to_u32(const void* p){
    uint32_t a;
    asm("{ .reg .u64 t; cvta.to.shared.u64 t, %1; cvt.u32.u64 %0, t; }" : "=r"(a) : "l"(p));
    return a;
}
__device__ __forceinline__ void cp_async16(uint32_t saddr, const void* gaddr){
    asm volatile("cp.async.cg.shared.global [%0], [%1], 16;" :: "r"(saddr), "l"(gaddr));
}
__device__ __forceinline__ void cp_commit(){ asm volatile("cp.async.commit_group;"); }
template<int N>
__device__ __forceinline__ void cp_wait(){ asm volatile("cp.async.wait_group %0;" :: "n"(N)); }

__device__ __forceinline__ void ldm_x4(uint32_t addr, uint32_t& r0, uint32_t& r1,
                                       uint32_t& r2, uint32_t& r3){
    asm volatile("ldmatrix.sync.aligned.m8n8.x4.shared.b16 {%0,%1,%2,%3}, [%4];"
        : "=r"(r0), "=r"(r1), "=r"(r2), "=r"(r3) : "r"(addr));
}
__device__ __forceinline__ void mma_bf16(float& c0, float& c1, float& c2, float& c3,
                                         uint32_t a0, uint32_t a1, uint32_t a2, uint32_t a3,
                                         uint32_t b0, uint32_t b1){
    asm volatile("mma.sync.aligned.m16n8k16.row.col.f32.bf16.bf16.f32 "
        "{%0,%1,%2,%3}, {%4,%5,%6,%7}, {%8,%9}, {%0,%1,%2,%3};"
        : "+f"(c0), "+f"(c1), "+f"(c2), "+f"(c3)
        : "r"(a0), "r"(a1), "r"(a2), "r"(a3), "r"(b0), "r"(b1));
}
__device__ __forceinline__ void split2(float f, __nv_bfloat16& h, __nv_bfloat16& l){
    h = __float2bfloat16(f);
    l = __float2bfloat16(f - __bfloat162float(h));
}

// ---------------- scratch (~2.3 GB) ----------------
__device__ __align__(256) float g_f0 [TOK*MDIM];          // h (residual)
__device__ __align__(256) float g_qkv[(size_t)TOK*1536];  // qkv / att_out / h1 / ff2
__device__ __align__(256) __nv_bfloat16 g_a1[(size_t)TOK*1024];  // split 512-wide acts
__device__ __align__(256) __nv_bfloat16 g_a2[(size_t)TOK*4096];  // split ff / x acts
__device__ __align__(256) __nv_bfloat16 g_win2 [512*256];
__device__ __align__(256) __nv_bfloat16 g_wqkv2[(size_t)1536*1024];
__device__ __align__(256) __nv_bfloat16 g_wo2  [512*1024];
__device__ __align__(256) __nv_bfloat16 g_wf12 [(size_t)2048*1024];
__device__ __align__(256) __nv_bfloat16 g_wf22 [(size_t)512*4096];
__device__ __align__(256) __nv_bfloat16 g_wout2[128*1024];

// ---------------- fused weight conversion (ONE launch for all 8) ----------
struct WtDesc { const float* W; __nv_bfloat16* Y; int K; int N; };
struct WtTable { WtDesc d[8]; };

__global__ void __launch_bounds__(256)
split_wt_all(WtTable tab)
{
    const WtDesc& e = tab.d[blockIdx.y];
    size_t total = (size_t)e.N * 2 * e.K;
    size_t id = (size_t)blockIdx.x * 256 + threadIdx.x;
    if (id >= total) return;
    int K2 = 2 * e.K;
    size_t n = id / K2;
    int c = (int)(id % K2);
    int reg = c >= e.K, cs = c - (reg ? e.K : 0);
    float x = e.W[(size_t)cs * e.N + n];
    __nv_bfloat16 h, l;
    split2(x, h, l);
    e.Y[id] = reg ? l : h;
}

// ---------------- split conversion: activations (x only) ----------------
__global__ void __launch_bounds__(256)
split_act(const float* __restrict__ X, __nv_bfloat16* __restrict__ Y,
          int K, size_t total /* R*K/4 */)
{
    size_t id = (size_t)blockIdx.x * 256 + threadIdx.x;
    if (id >= total) return;
    int kq = K >> 2;
    size_t r = id / kq;
    int c = (int)(id % kq) << 2;
    float4 x = *(const float4*)(X + r * K + c);
    __nv_bfloat16 h0,h1,h2,h3,l0,l1,l2,l3;
    split2(x.x,h0,l0); split2(x.y,h1,l1); split2(x.z,h2,l2); split2(x.w,h3,l3);
    __nv_bfloat162 hA = __halves2bfloat162(h0,h1), hB = __halves2bfloat162(h2,h3);
    __nv_bfloat162 lA = __halves2bfloat162(l0,l1), lB = __halves2bfloat162(l2,l3);
    size_t ob = r * (size_t)(2 * K);
    *(uint2*)(Y + ob + c)     = make_uint2(*(uint32_t*)&hA, *(uint32_t*)&hB);
    *(uint2*)(Y + ob + K + c) = make_uint2(*(uint32_t*)&lA, *(uint32_t*)&lB);
}

// ---------------- mma.sync bf16 GEMM, 3-segment split schedule ----------------
// (round-13 configuration: proven best)
// A [M, 2K] = [hi|lo], Bt [Ntot, 2K] = [hi|lo] (K-major rows).
// Segments: (Ahi,Bhi), (Alo,Bhi), (Ahi,Blo) accumulated in registers.
// CTA tile 128x128; 4 warps (2x2); warp tile 64x64; BK=64; 144-byte row
// stride (affine, conflict-free); 2 symmetric stages (36.9KB each);
// 128 threads, 73.7KB smem -> 3 CTAs/SM.
// mode: 0=f32, 1=silu+split, 2=f32+split.
__global__ void __launch_bounds__(128, 3)
mma_gemm(const __nv_bfloat16* __restrict__ A, const __nv_bfloat16* __restrict__ Bt,
         float* __restrict__ Cf, __nv_bfloat16* __restrict__ Csp,
         int K, int Ntot, int mode)
{
    constexpr int THREADS = 128;
    constexpr int ROWB = 144;                 // bytes per smem row
    constexpr int A_BYTES = 128 * ROWB;       // 18432
    constexpr int STAGE_BYTES = 256 * ROWB;   // 36864
    extern __shared__ __align__(16) char smem[];

    const int tid  = threadIdx.x;
    const int lane = tid & 31;
    const int wid  = tid >> 5;
    const int wm   = wid >> 1;        // 0..1
    const int wn   = wid & 1;         // 0..1
    const int m0   = blockIdx.y * 128;
    const int n0   = blockIdx.x * 128;

    const int lda = 2 * K;
    const __nv_bfloat16* Ab = A  + (size_t)m0 * lda;
    const __nv_bfloat16* Bb = Bt + (size_t)n0 * lda;
    const uint32_t sbase = smem_to_u32(smem);

    float c[4][8][4];
    #pragma unroll
    for (int i = 0; i < 4; i++)
        #pragma unroll
        for (int j = 0; j < 8; j++)
            #pragma unroll
            for (int q = 0; q < 4; q++) c[i][j][q] = 0.f;

    const int kch = K >> 6;       // chunks of 64 columns
    const int nch = 3 * kch;

    auto load_chunk = [&](int tt, int stage){
        int seg = (tt >= kch) + (tt >= 2 * kch);
        int kk = tt - seg * kch;
        int ac = ((seg == 1) ? K : 0) + (kk << 6);
        int bc = ((seg == 2) ? K : 0) + (kk << 6);
        uint32_t sa = sbase + stage * STAGE_BYTES;
        uint32_t sb = sa + A_BYTES;
        #pragma unroll
        for (int it = 0; it < 8; it++){
            int idx = tid + it * THREADS;
            int r = idx >> 3, ch = idx & 7;
            cp_async16(sa + r * ROWB + ch * 16, Ab + (size_t)r * lda + ac + ch * 8);
        }
        #pragma unroll
        for (int it = 0; it < 8; it++){
            int idx = tid + it * THREADS;
            int r = idx >> 3, ch = idx & 7;
            cp_async16(sb + r * ROWB + ch * 16, Bb + (size_t)r * lda + bc + ch * 8);
        }
    };

    load_chunk(0, 0);
    cp_commit();

    for (int t = 0; t < nch; t++){
        cp_wait<0>();
        __syncthreads();
        if (t + 1 < nch){
            load_chunk(t + 1, (t + 1) & 1);
            cp_commit();
        }
        const uint32_t sa = sbase + (t & 1) * STAGE_BYTES;
        const uint32_t sb = sa + A_BYTES;
        #pragma unroll
        for (int ks = 0; ks < 4; ks++){
            uint32_t a[4][4], b[8][2];
            #pragma unroll
            for (int mf = 0; mf < 4; mf++){
                int r = wm * 64 + mf * 16 + (lane & 15);
                int ch = 2 * ks + (lane >> 4);
                ldm_x4(sa + r * ROWB + ch * 16,
                       a[mf][0], a[mf][1], a[mf][2], a[mf][3]);
            }
            #pragma unroll
            for (int g = 0; g < 4; g++){
                int r = wn * 64 + g * 16 + ((lane >> 4) << 3) + (lane & 7);
                int ch = 2 * ks + ((lane >> 3) & 1);
                ldm_x4(sb + r * ROWB + ch * 16,
                       b[2*g][0], b[2*g][1], b[2*g+1][0], b[2*g+1][1]);
            }
            #pragma unroll
            for (int mf = 0; mf < 4; mf++)
                #pragma unroll
                for (int nf = 0; nf < 8; nf++)
                    mma_bf16(c[mf][nf][0], c[mf][nf][1], c[mf][nf][2], c[mf][nf][3],
                             a[mf][0], a[mf][1], a[mf][2], a[mf][3],
                             b[nf][0], b[nf][1]);
        }
    }

    // epilogue
    #pragma unroll
    for (int mf = 0; mf < 4; mf++){
        #pragma unroll
        for (int half = 0; half < 2; half++){
            const int row = m0 + wm * 64 + mf * 16 + (lane >> 2) + half * 8;
            #pragma unroll
            for (int nf = 0; nf < 8; nf++){
                const int col = n0 + wn * 64 + nf * 8 + (lane & 3) * 2;
                float fx = c[mf][nf][half * 2 + 0];
                float fy = c[mf][nf][half * 2 + 1];
                if (mode == 1){
                    fx = fx / (1.f + __expf(-fx));
                    fy = fy / (1.f + __expf(-fy));
                }
                if (mode != 1){
                    *(float2*)&Cf[(size_t)row * Ntot + col] = make_float2(fx, fy);
                }
                if (mode != 0){
                    __nv_bfloat16 hx, hy, lx, ly;
                    split2(fx, hx, lx);
                    split2(fy, hy, ly);
                    __nv_bfloat162 hp = __halves2bfloat162(hx, hy);
                    __nv_bfloat162 lp = __halves2bfloat162(lx, ly);
                    size_t rb = (size_t)row * (2 * Ntot);
                    *(__nv_bfloat162*)&Csp[rb + col]        = hp;
                    *(__nv_bfloat162*)&Csp[rb + Ntot + col] = lp;
                }
            }
        }
    }
}

// ---------------- fused attention: one block per m, all 8 heads ------------
__global__ void __launch_bounds__(256)
attn_kernel(const float* __restrict__ qkv,
            const int*   __restrict__ dist, const int* __restrict__ phi,
            const float* __restrict__ dtab, const float* __restrict__ ptab,
            const float* __restrict__ Wb,   __nv_bfloat16* __restrict__ osp)
{
    extern __shared__ float sm[];
    float* bias8 = sm;              // [h*1056 + i*33 + j]  (8448)
    float* qs    = sm + 8448;       // [i*68 + d]           (2176)
    float* ks    = sm + 10624;      // (2176)
    float* vs    = sm + 12800;      // (2176)
    float* sc    = sm + 14976;      // [i*33 + j]           (1056)
    float* wb8   = sm + 16032;      // [p*8 + h]            (256)

    const int m = blockIdx.x;
    const int t = threadIdx.x;

    wb8[t] = Wb[t];                 // 256 = PED*HEADS
    __syncthreads();

    // ---- bias for all heads: 4 pairs per thread ----
    const int base_mm = m * (NH * NH);
    #pragma unroll
    for (int q4 = 0; q4 < 4; q4++){
        int pair = t * 4 + q4;              // 0..1023
        int i = pair >> 5, j = pair & 31;
        int id = dist[base_mm + pair];
        int ip = phi [base_mm + pair];
        const float4* dp = (const float4*)(dtab + (size_t)id * 32);
        const float4* fp = (const float4*)(ptab + (size_t)ip * 32);
        float acc[8];
        #pragma unroll
        for (int h = 0; h < 8; h++) acc[h] = 0.f;
        #pragma unroll
        for (int v4 = 0; v4 < 8; v4++){
            float4 d4 = dp[v4];
            float4 f4 = fp[v4];
            float pr[4] = { d4.x*f4.x, d4.y*f4.y, d4.z*f4.z, d4.w*f4.w };
            #pragma unroll
            for (int pp = 0; pp < 4; pp++){
                int p = v4 * 4 + pp;
                #pragma unroll
                for (int h = 0; h < 8; h++)
                    acc[h] += pr[pp] * wb8[p * 8 + h];
            }
        }
        #pragma unroll
        for (int h = 0; h < 8; h++) bias8[h * 1056 + i * 33 + j] = acc[h];
    }

    const int i = t >> 3;          // row 0..31
    const int g = t & 7;           // group 0..7

    for (int h = 0; h < 8; h++){
        __syncthreads();   // bias ready (h=0) / prior head done (h>0)
        // load q,k,v head slices (32 rows x 16 float4 each), vectorized
        #pragma unroll
        for (int it = 0; it < 2; it++){
            int idx = t + it * 256;        // 0..511
            int r  = idx >> 4;             // row 0..31
            int c4 = idx & 15;             // float4 within row 0..15
            size_t gb = (size_t)(m * NH + r) * 1536 + h * 64 + c4 * 4;
            *(float4*)(qs + r * 68 + c4 * 4) = *(const float4*)(qkv + gb);
            *(float4*)(ks + r * 68 + c4 * 4) = *(const float4*)(qkv + gb + 512);
            *(float4*)(vs + r * 68 + c4 * 4) = *(const float4*)(qkv + gb + 1024);
        }
        __syncthreads();

        // scores: 4 j's per thread; q row loaded once per d4 (outer d loop)
        float sv[4] = {0.f, 0.f, 0.f, 0.f};
        #pragma unroll
        for (int d4 = 0; d4 < 16; d4++){
            float4 qa = *(float4*)(qs + i * 68 + d4 * 4);
            #pragma unroll
            for (int jj = 0; jj < 4; jj++){
                float4 ka = *(float4*)(ks + (g * 4 + jj) * 68 + d4 * 4);
                sv[jj] += qa.x*ka.x + qa.y*ka.y + qa.z*ka.z + qa.w*ka.w;
            }
        }
        #pragma unroll
        for (int jj = 0; jj < 4; jj++)
            sv[jj] = sv[jj] * 0.125f + bias8[h * 1056 + i * 33 + g * 4 + jj];

        // softmax across the 8 threads of row i
        float mx = fmaxf(fmaxf(sv[0], sv[1]), fmaxf(sv[2], sv[3]));
        mx = fmaxf(mx, __shfl_xor_sync(0xffffffffu, mx, 1));
        mx = fmaxf(mx, __shfl_xor_sync(0xffffffffu, mx, 2));
        mx = fmaxf(mx, __shfl_xor_sync(0xffffffffu, mx, 4));
        float ev[4], sum = 0.f;
        #pragma unroll
        for (int jj = 0; jj < 4; jj++){ ev[jj] = __expf(sv[jj] - mx); sum += ev[jj]; }
        sum += __shfl_xor_sync(0xffffffffu, sum, 1);
        sum += __shfl_xor_sync(0xffffffffu, sum, 2);
        sum += __shfl_xor_sync(0xffffffffu, sum, 4);
        const float inv = 1.f / sum;
        #pragma unroll
        for (int jj = 0; jj < 4; jj++) sc[i * 33 + g * 4 + jj] = ev[jj] * inv;
        __syncwarp();

        // AV: thread owns d-segment g*8 .. g*8+7 of row i
        const int dseg = g * 8;
        float acc[8];
        #pragma unroll
        for (int dd = 0; dd < 8; dd++) acc[dd] = 0.f;
        for (int j = 0; j < NH; j++){
            float p = sc[i * 33 + j];
            float4 v0 = *(float4*)(vs + j * 68 + dseg);
            float4 v1 = *(float4*)(vs + j * 68 + dseg + 4);
            acc[0] += p * v0.x; acc[1] += p * v0.y;
            acc[2] += p * v0.z; acc[3] += p * v0.w;
            acc[4] += p * v1.x; acc[5] += p * v1.y;
            acc[6] += p * v1.z; acc[7] += p * v1.w;
        }
        // split-bf16 output, row stride 1024 = [hi(512) | lo(512)]
        size_t rb = ((size_t)(m * NH) + i) * 1024 + h * 64 + dseg;
        #pragma unroll
        for (int dd = 0; dd < 8; dd += 2){
            __nv_bfloat16 hx, hy, lx, ly;
            split2(acc[dd],   hx, lx);
            split2(acc[dd+1], hy, ly);
            *(__nv_bfloat162*)&osp[rb + dd]       = __halves2bfloat162(hx, hy);
            *(__nv_bfloat162*)&osp[rb + 512 + dd] = __halves2bfloat162(lx, ly);
        }
    }
}

// ---------------- fused residual add + LayerNorm (+optional split out) ----
__global__ void __launch_bounds__(128)
add_ln_kernel2(const float* __restrict__ a, const float* __restrict__ b,
               const float* __restrict__ g, const float* __restrict__ be,
               float* __restrict__ outf, __nv_bfloat16* __restrict__ outsp)
{
    const int row = blockIdx.x;
    const int t   = threadIdx.x;
    const size_t off = (size_t)row * MDIM + t * 4;

    float4 va = *(const float4*)(a + off);
    float4 vb = *(const float4*)(b + off);
    float4 vv = make_float4(va.x + vb.x, va.y + vb.y, va.z + vb.z, va.w + vb.w);

    float s  = vv.x + vv.y + vv.z + vv.w;
    float ss = vv.x*vv.x + vv.y*vv.y + vv.z*vv.z + vv.w*vv.w;
    #pragma unroll
    for (int o2 = 16; o2; o2 >>= 1){
        s  += __shfl_xor_sync(0xffffffffu, s,  o2);
        ss += __shfl_xor_sync(0xffffffffu, ss, o2);
    }
    __shared__ float sh_s[4], sh_ss[4];
    const int w = t >> 5, l = t & 31;
    if (l == 0){ sh_s[w] = s; sh_ss[w] = ss; }
    __syncthreads();
    s  = sh_s[0]  + sh_s[1]  + sh_s[2]  + sh_s[3];
    ss = sh_ss[0] + sh_ss[1] + sh_ss[2] + sh_ss[3];

    const float mean = s * (1.f / 512.f);
    const float var  = ss * (1.f / 512.f) - mean * mean;
    const float rstd = rsqrtf(var + 1e-5f);

    float4 vg  = *(const float4*)(g  + t*4);
    float4 vbe = *(const float4*)(be + t*4);
    float4 r;
    r.x = (vv.x - mean) * rstd * vg.x + vbe.x;
    r.y = (vv.y - mean) * rstd * vg.y + vbe.y;
    r.z = (vv.z - mean) * rstd * vg.z + vbe.z;
    r.w = (vv.w - mean) * rstd * vg.w + vbe.w;
    if (outf) *(float4*)(outf + off) = r;
    if (outsp){
        __nv_bfloat16 h0,h1,h2,h3,l0,l1,l2,l3;
        split2(r.x,h0,l0); split2(r.y,h1,l1); split2(r.z,h2,l2); split2(r.w,h3,l3);
        __nv_bfloat162 hA = __halves2bfloat162(h0,h1), hB = __halves2bfloat162(h2,h3);
        __nv_bfloat162 lA = __halves2bfloat162(l0,l1), lB = __halves2bfloat162(l2,l3);
        size_t rb = (size_t)row * 1024 + t * 4;
        *(uint2*)(outsp + rb)       = make_uint2(*(uint32_t*)&hA, *(uint32_t*)&hB);
        *(uint2*)(outsp + rb + 512) = make_uint2(*(uint32_t*)&lA, *(uint32_t*)&lB);
    }
}

// ---------------- driver ----------------
extern "C" void kernel_launch(void* const* d_in, const int* in_sizes, int n_in,
                              void* d_out, int out_size)
{
    (void)in_sizes; (void)n_in; (void)out_size;

    const float* x    = (const float*)d_in[0];
    const int*   dist = (const int*)  d_in[1];
    const int*   phis = (const int*)  d_in[2];
    const float* W_in = (const float*)d_in[3];
    const float* dtab = (const float*)d_in[4];
    const float* ptab = (const float*)d_in[5];
    const float* Wb   = (const float*)d_in[6];
    const float* Wq   = (const float*)d_in[7];
    const float* Wk   = (const float*)d_in[8];
    const float* Wv   = (const float*)d_in[9];
    const float* Wo   = (const float*)d_in[10];
    const float* Wf1  = (const float*)d_in[11];
    const float* Wf2  = (const float*)d_in[12];
    const float* g1   = (const float*)d_in[13];
    const float* b1   = (const float*)d_in[14];
    const float* g2   = (const float*)d_in[15];
    const float* b2   = (const float*)d_in[16];
    const float* Wout = (const float*)d_in[17];
    float* out = (float*)d_out;

    float *pf0, *pqkv;
    __nv_bfloat16 *pa1, *pa2, *pwin, *pwqkv, *pwo, *pwf1, *pwf2, *pwout;
    cudaGetSymbolAddress((void**)&pf0,  g_f0);
    cudaGetSymbolAddress((void**)&pqkv, g_qkv);
    cudaGetSymbolAddress((void**)&pa1,  g_a1);
    cudaGetSymbolAddress((void**)&pa2,  g_a2);
    cudaGetSymbolAddress((void**)&pwin, g_win2);
    cudaGetSymbolAddress((void**)&pwqkv,g_wqkv2);
    cudaGetSymbolAddress((void**)&pwo,  g_wo2);
    cudaGetSymbolAddress((void**)&pwf1, g_wf12);
    cudaGetSymbolAddress((void**)&pwf2, g_wf22);
    cudaGetSymbolAddress((void**)&pwout,g_wout2);

    float* att_out = pqkv;                       // aliases (sequential deps)
    float* h1      = pqkv + (size_t)TOK * 512;
    float* ff2     = pqkv + (size_t)TOK * 1024;

    const int SMG = 2 * 256 * 144;          // 73728 per CTA (3 CTAs/SM)
    const int SMA = 16288 * 4;              // 65152 (attention)
    cudaFuncSetAttribute(mma_gemm, cudaFuncAttributeMaxDynamicSharedMemorySize, SMG);
    cudaFuncSetAttribute(attn_kernel, cudaFuncAttributeMaxDynamicSharedMemorySize, SMA);

    const unsigned MT = TOK / 128;   // 1024 m-tiles

    // 0) all weight conversions in one launch
    WtTable tab;
    tab.d[0] = { W_in, pwin,                      128,  512 };
    tab.d[1] = { Wq,   pwqkv,                     512,  512 };
    tab.d[2] = { Wk,   pwqkv + (size_t)512*1024,  512,  512 };
    tab.d[3] = { Wv,   pwqkv + (size_t)1024*1024, 512,  512 };
    tab.d[4] = { Wo,   pwo,                       512,  512 };
    tab.d[5] = { Wf1,  pwf1,                      512, 2048 };
    tab.d[6] = { Wf2,  pwf2,                     2048,  512 };
    tab.d[7] = { Wout, pwout,                     512,  128 };
    split_wt_all<<<dim3(8192, 8), 256>>>(tab);

    // 1) split x -> a2  [TOK, 256]
    {
        size_t total = (size_t)TOK * 128 / 4;
        split_act<<<(unsigned)((total + 255) / 256), 256>>>(x, pa2, 128, total);
    }
    // 2) h = x @ W_in -> f0 (fp32) + split -> a1
    mma_gemm<<<dim3(4, MT), 128, SMG>>>(pa2, pwin, pf0, pa1, 128, 512, 2);
    // 3) qkv = h @ Wqkv -> fp32 [TOK,1536]
    mma_gemm<<<dim3(12, MT), 128, SMG>>>(pa1, pwqkv, pqkv, nullptr, 512, 1536, 0);
    // 4) attention -> split o -> a1
    attn_kernel<<<MCNT, 256, SMA>>>(pqkv, dist, phis, dtab, ptab, Wb, pa1);
    // 5) att_out = o @ Wo -> fp32
    mma_gemm<<<dim3(4, MT), 128, SMG>>>(pa1, pwo, att_out, nullptr, 512, 512, 0);
    // 6) h1 = LN(h + att_out) -> fp32 h1 + split -> a1
    add_ln_kernel2<<<TOK, 128>>>(pf0, att_out, g1, b1, h1, pa1);
    // 7) ff = silu(h1 @ Wf1) -> split -> a2
    mma_gemm<<<dim3(16, MT), 128, SMG>>>(pa1, pwf1, nullptr, pa2, 512, 2048, 1);
    // 8) ff2 = ff @ Wf2 -> fp32
    mma_gemm<<<dim3(4, MT), 128, SMG>>>(pa2, pwf2, ff2, nullptr, 2048, 512, 0);
    // 9) h2 = LN(h1 + ff2) -> split only -> a1
    add_ln_kernel2<<<TOK, 128>>>(h1, ff2, g2, b2, nullptr, pa1);
    // 10) out = h2 @ W_out
    mma_gemm<<<dim3(1, MT), 128, SMG>>>(pa1, pwout, out, nullptr, 512, 128, 0);
}